// round 1
// baseline (speedup 1.0000x reference)
#include <cuda_runtime.h>
#include <cuda_bf16.h>
#include <math.h>

#define B_    4
#define S_    2048
#define E_    1024
#define H_    16
#define DH_   64
// derived
#define M_TOK (B_*S_)          // 8192
#define HD_   (H_*DH_)         // 1024

// ---------------- scratch (device globals; no runtime alloc allowed) --------
__device__ float g_q[B_*H_*S_*DH_];   // [B,H,S,Dh]
__device__ float g_k[B_*H_*S_*DH_];
__device__ float g_v[B_*H_*S_*DH_];
__device__ float g_z[M_TOK*HD_];      // [B,S,H*Dh]

// ============================================================================
// Kernel 1: fused QKV projection GEMM.
//   A = x [8192,1024], logical B = [1024, 3*1024] built from Wq/Wk/Wv [H,E,Dh]
//   Tiles: BM=128, BN=64, BK=16; 256 threads; 8x4 micro-tile per thread.
//   N-tiles (64 wide) align exactly with one (which, head) pair.
// ============================================================================
__global__ __launch_bounds__(256) void qkv_gemm(
    const float* __restrict__ x,
    const float* __restrict__ Wq, const float* __restrict__ bq,
    const float* __restrict__ Wk, const float* __restrict__ bk,
    const float* __restrict__ Wv, const float* __restrict__ bv)
{
    __shared__ float At[16][132];   // A transposed [k][m], padded
    __shared__ float Bs[16][68];    // B natural [k][n], padded

    const int tid = threadIdx.x;
    const int tx = tid & 15;        // 0..15 -> 4 output cols
    const int ty = tid >> 4;        // 0..15 -> 8 output rows
    const int mBase = blockIdx.y * 128;
    const int nBase = blockIdx.x * 64;

    const int which = nBase >> 10;           // 0=q 1=k 2=v
    const int h     = (nBase & 1023) >> 6;   // head
    const float* W    = (which == 0 ? Wq : which == 1 ? Wk : Wv) + h * (E_*DH_);
    const float* bias = (which == 0 ? bq : which == 1 ? bk : bv) + h * DH_;
    float* outp       = (which == 0 ? g_q : which == 1 ? g_k : g_v);

    // loader indices
    const int la_k = (tid & 3) * 4;   // float4 col within BK
    const int la_m = tid >> 2;        // 0..63 (+64 second pass)
    const int lb_n = tid & 63;
    const int lb_k = tid >> 6;        // 0..3 (+4 per pass)

    float acc[8][4];
    #pragma unroll
    for (int i = 0; i < 8; i++)
        #pragma unroll
        for (int j = 0; j < 4; j++) acc[i][j] = 0.f;

    for (int k0 = 0; k0 < E_; k0 += 16) {
        // A tile: x[mBase+m][k0+la_k ..+3] -> At[k][m]
        #pragma unroll
        for (int p = 0; p < 2; p++) {
            int m = la_m + p * 64;
            float4 a = *(const float4*)&x[(size_t)(mBase + m) * E_ + k0 + la_k];
            At[la_k + 0][m] = a.x;
            At[la_k + 1][m] = a.y;
            At[la_k + 2][m] = a.z;
            At[la_k + 3][m] = a.w;
        }
        // B tile: W[e][d] (e = k0+kk, d = n_local), coalesced over d
        #pragma unroll
        for (int p = 0; p < 4; p++) {
            int kk = lb_k + p * 4;
            Bs[kk][lb_n] = W[(size_t)(k0 + kk) * DH_ + lb_n];
        }
        __syncthreads();

        #pragma unroll
        for (int kk = 0; kk < 16; kk++) {
            float4 a0 = *(const float4*)&At[kk][ty * 8];
            float4 a1 = *(const float4*)&At[kk][ty * 8 + 4];
            float4 b  = *(const float4*)&Bs[kk][tx * 4];
            float a[8] = {a0.x, a0.y, a0.z, a0.w, a1.x, a1.y, a1.z, a1.w};
            float bb[4] = {b.x, b.y, b.z, b.w};
            #pragma unroll
            for (int i = 0; i < 8; i++)
                #pragma unroll
                for (int j = 0; j < 4; j++)
                    acc[i][j] += a[i] * bb[j];
        }
        __syncthreads();
    }

    float bv4[4];
    #pragma unroll
    for (int j = 0; j < 4; j++) bv4[j] = bias[tx * 4 + j];

    #pragma unroll
    for (int i = 0; i < 8; i++) {
        int m = mBase + ty * 8 + i;
        int bb = m >> 11;           // / 2048
        int s  = m & 2047;
        float4 r;
        r.x = acc[i][0] + bv4[0];
        r.y = acc[i][1] + bv4[1];
        r.z = acc[i][2] + bv4[2];
        r.w = acc[i][3] + bv4[3];
        *(float4*)&outp[(size_t)((bb * H_ + h) * S_ + s) * DH_ + tx * 4] = r;
    }
}

// ============================================================================
// Kernel 2: flash attention per (b,h). BM=64 queries/block, BN=64 key tile.
//   256 threads, 4x4 micro-tile. Online softmax, P tile aliases K^T tile.
//   Writes z in [B, S, H*Dh] layout for the output projection.
// ============================================================================
__global__ __launch_bounds__(256) void attn_kernel(
    const float* __restrict__ q, const float* __restrict__ k,
    const float* __restrict__ v, float* __restrict__ z)
{
    extern __shared__ float smem[];
    float* Qt  = smem;                 // [64][68]  Q^T [d][r], pre-scaled
    float* KtP = smem + 64 * 68;       // [64][68]  K^T [d][c], later P [r][c]
    float* Vs  = smem + 2 * 64 * 68;   // [64][68]  V  [c][d]

    const int tid = threadIdx.x;
    const int tx = tid & 15;
    const int ty = tid >> 4;
    const int bh = blockIdx.y;
    const int qBase = blockIdx.x * 64;

    const float* qp = q + (size_t)bh * S_ * DH_;
    const float* kp = k + (size_t)bh * S_ * DH_;
    const float* vp = v + (size_t)bh * S_ * DH_;

    const int ld_d = tid & 63;
    const int ld_r = tid >> 6;   // 0..3, 16 passes

    // Load Q tile transposed, fold in softmax scale 1/sqrt(64)=0.125
    #pragma unroll
    for (int p = 0; p < 16; p++) {
        int r = ld_r + p * 4;
        Qt[ld_d * 68 + r] = qp[(size_t)(qBase + r) * DH_ + ld_d] * 0.125f;
    }

    float o[4][4];
    float m_i[4], l_i[4];
    #pragma unroll
    for (int i = 0; i < 4; i++) {
        m_i[i] = -3.0e38f; l_i[i] = 0.f;
        #pragma unroll
        for (int j = 0; j < 4; j++) o[i][j] = 0.f;
    }

    for (int jt = 0; jt < S_ / 64; jt++) {
        const int kBase = jt * 64;
        __syncthreads();   // previous iter's KtP(P)/Vs reads done
        #pragma unroll
        for (int p = 0; p < 16; p++) {
            int c = ld_r + p * 4;
            KtP[ld_d * 68 + c] = kp[(size_t)(kBase + c) * DH_ + ld_d];
            Vs[c * 68 + ld_d]  = vp[(size_t)(kBase + c) * DH_ + ld_d];
        }
        __syncthreads();

        // GEMM1: S = Q K^T  (contraction over d)
        float sc[4][4];
        #pragma unroll
        for (int i = 0; i < 4; i++)
            #pragma unroll
            for (int j = 0; j < 4; j++) sc[i][j] = 0.f;

        #pragma unroll 8
        for (int d = 0; d < 64; d++) {
            float4 a = *(const float4*)&Qt[d * 68 + ty * 4];
            float4 b = *(const float4*)&KtP[d * 68 + tx * 4];
            float av[4] = {a.x, a.y, a.z, a.w};
            float bvv[4] = {b.x, b.y, b.z, b.w};
            #pragma unroll
            for (int i = 0; i < 4; i++)
                #pragma unroll
                for (int j = 0; j < 4; j++)
                    sc[i][j] += av[i] * bvv[j];
        }

        // Online softmax update per row (reduce across the 16 tx lanes)
        #pragma unroll
        for (int i = 0; i < 4; i++) {
            float mx = fmaxf(fmaxf(sc[i][0], sc[i][1]), fmaxf(sc[i][2], sc[i][3]));
            #pragma unroll
            for (int off = 8; off > 0; off >>= 1)
                mx = fmaxf(mx, __shfl_xor_sync(0xffffffffu, mx, off));
            float mnew = fmaxf(m_i[i], mx);
            float corr = __expf(m_i[i] - mnew);
            m_i[i] = mnew;
            float rs = 0.f;
            #pragma unroll
            for (int j = 0; j < 4; j++) {
                sc[i][j] = __expf(sc[i][j] - mnew);
                rs += sc[i][j];
            }
            #pragma unroll
            for (int off = 8; off > 0; off >>= 1)
                rs += __shfl_xor_sync(0xffffffffu, rs, off);
            l_i[i] = l_i[i] * corr + rs;
            #pragma unroll
            for (int j = 0; j < 4; j++) o[i][j] *= corr;
        }

        __syncthreads();   // all GEMM1 reads of KtP done
        // write P (natural layout) into KtP
        #pragma unroll
        for (int i = 0; i < 4; i++) {
            float4 r = make_float4(sc[i][0], sc[i][1], sc[i][2], sc[i][3]);
            *(float4*)&KtP[(ty * 4 + i) * 68 + tx * 4] = r;
        }
        __syncthreads();

        // GEMM2: O += P V  (contraction over key index n)
        #pragma unroll 8
        for (int n = 0; n < 64; n++) {
            float4 vv = *(const float4*)&Vs[n * 68 + tx * 4];
            float pv[4];
            #pragma unroll
            for (int i = 0; i < 4; i++) pv[i] = KtP[(ty * 4 + i) * 68 + n];
            #pragma unroll
            for (int i = 0; i < 4; i++) {
                o[i][0] += pv[i] * vv.x;
                o[i][1] += pv[i] * vv.y;
                o[i][2] += pv[i] * vv.z;
                o[i][3] += pv[i] * vv.w;
            }
        }
    }

    // Epilogue: normalize and write z[b][s][h*64+d]
    const int bb = bh >> 4;
    const int hh = bh & 15;
    #pragma unroll
    for (int i = 0; i < 4; i++) {
        float inv = 1.0f / l_i[i];
        int s = qBase + ty * 4 + i;
        float4 r = make_float4(o[i][0] * inv, o[i][1] * inv,
                               o[i][2] * inv, o[i][3] * inv);
        *(float4*)&z[(size_t)(bb * S_ + s) * HD_ + hh * DH_ + tx * 4] = r;
    }
}

// ============================================================================
// Kernel 3: output projection GEMM: out = z @ Wo + bo
//   [8192,1024] @ [1024,1024]; same tiling as K1.
// ============================================================================
__global__ __launch_bounds__(256) void out_gemm(
    const float* __restrict__ zin, const float* __restrict__ Wo,
    const float* __restrict__ bo, float* __restrict__ out)
{
    __shared__ float At[16][132];
    __shared__ float Bs[16][68];

    const int tid = threadIdx.x;
    const int tx = tid & 15;
    const int ty = tid >> 4;
    const int mBase = blockIdx.y * 128;
    const int nBase = blockIdx.x * 64;

    const int la_k = (tid & 3) * 4;
    const int la_m = tid >> 2;
    const int lb_n = tid & 63;
    const int lb_k = tid >> 6;

    float acc[8][4];
    #pragma unroll
    for (int i = 0; i < 8; i++)
        #pragma unroll
        for (int j = 0; j < 4; j++) acc[i][j] = 0.f;

    for (int k0 = 0; k0 < HD_; k0 += 16) {
        #pragma unroll
        for (int p = 0; p < 2; p++) {
            int m = la_m + p * 64;
            float4 a = *(const float4*)&zin[(size_t)(mBase + m) * HD_ + k0 + la_k];
            At[la_k + 0][m] = a.x;
            At[la_k + 1][m] = a.y;
            At[la_k + 2][m] = a.z;
            At[la_k + 3][m] = a.w;
        }
        #pragma unroll
        for (int p = 0; p < 4; p++) {
            int kk = lb_k + p * 4;
            Bs[kk][lb_n] = Wo[(size_t)(k0 + kk) * E_ + nBase + lb_n];
        }
        __syncthreads();

        #pragma unroll
        for (int kk = 0; kk < 16; kk++) {
            float4 a0 = *(const float4*)&At[kk][ty * 8];
            float4 a1 = *(const float4*)&At[kk][ty * 8 + 4];
            float4 b  = *(const float4*)&Bs[kk][tx * 4];
            float a[8] = {a0.x, a0.y, a0.z, a0.w, a1.x, a1.y, a1.z, a1.w};
            float bb[4] = {b.x, b.y, b.z, b.w};
            #pragma unroll
            for (int i = 0; i < 8; i++)
                #pragma unroll
                for (int j = 0; j < 4; j++)
                    acc[i][j] += a[i] * bb[j];
        }
        __syncthreads();
    }

    float bv4[4];
    #pragma unroll
    for (int j = 0; j < 4; j++) bv4[j] = bo[nBase + tx * 4 + j];

    #pragma unroll
    for (int i = 0; i < 8; i++) {
        int m = mBase + ty * 8 + i;
        float4 r;
        r.x = acc[i][0] + bv4[0];
        r.y = acc[i][1] + bv4[1];
        r.z = acc[i][2] + bv4[2];
        r.w = acc[i][3] + bv4[3];
        *(float4*)&out[(size_t)m * E_ + nBase + tx * 4] = r;
    }
}

// ============================================================================
// Launch
// ============================================================================
extern "C" void kernel_launch(void* const* d_in, const int* in_sizes, int n_in,
                              void* d_out, int out_size)
{
    const float* x  = (const float*)d_in[0];
    const float* Wq = (const float*)d_in[1];
    const float* bq = (const float*)d_in[2];
    const float* Wk = (const float*)d_in[3];
    const float* bk = (const float*)d_in[4];
    const float* Wv = (const float*)d_in[5];
    const float* bv = (const float*)d_in[6];
    const float* Wo = (const float*)d_in[7];
    const float* bo = (const float*)d_in[8];
    float* out = (float*)d_out;

    float *qptr, *kptr, *vptr, *zptr;
    cudaGetSymbolAddress((void**)&qptr, g_q);
    cudaGetSymbolAddress((void**)&kptr, g_k);
    cudaGetSymbolAddress((void**)&vptr, g_v);
    cudaGetSymbolAddress((void**)&zptr, g_z);

    // attention kernel needs 51 KB dynamic smem
    const int attn_smem = 3 * 64 * 68 * (int)sizeof(float);
    cudaFuncSetAttribute(attn_kernel,
                         cudaFuncAttributeMaxDynamicSharedMemorySize, attn_smem);

    // K1: QKV projection. grid = (N tiles 3072/64, M tiles 8192/128)
    qkv_gemm<<<dim3(48, 64), 256>>>(x, Wq, bq, Wk, bk, Wv, bv);

    // K2: flash attention. grid = (S/64, B*H)
    attn_kernel<<<dim3(S_ / 64, B_ * H_), 256, attn_smem>>>(qptr, kptr, vptr, zptr);

    // K3: output projection. grid = (1024/64, 8192/128)
    out_gemm<<<dim3(16, 64), 256>>>(zptr, Wo, bo, out);
}

// round 5
// speedup vs baseline: 1.5315x; 1.5315x over previous
#include <cuda_runtime.h>
#include <cuda_bf16.h>
#include <math.h>

#define B_    4
#define S_    2048
#define E_    1024
#define H_    16
#define DH_   64
#define MT    (B_*S_)        // 8192 tokens
#define HD    (H_*DH_)       // 1024
#define NQKV  (3*HD)         // 3072

typedef __nv_bfloat16 bf16;

// ---------------- split scratch buffers (device globals) --------------------
__device__ bf16 g_xh[MT*E_],  g_xl[MT*E_];          // x   [8192][1024]
__device__ bf16 g_Wah[E_*NQKV], g_Wal[E_*NQKV];     // QKV weights [k=1024][n=3072]
__device__ bf16 g_Woh[HD*E_], g_Wol[HD*E_];         // Wo  [k=1024][n=1024]
__device__ float g_bias[NQKV];                      // gathered qkv bias
__device__ bf16 g_qh[B_*H_*S_*DH_], g_ql[B_*H_*S_*DH_];
__device__ bf16 g_kh[B_*H_*S_*DH_], g_kl[B_*H_*S_*DH_];
__device__ bf16 g_vh[B_*H_*S_*DH_], g_vl[B_*H_*S_*DH_];
__device__ bf16 g_zh[MT*HD],  g_zl[MT*HD];          // z   [8192][1024]

// ---------------- helpers ---------------------------------------------------
__device__ __forceinline__ void split1(float v, bf16* h, bf16* l) {
    bf16 hh = __float2bfloat16(v);
    *h = hh;
    *l = __float2bfloat16(v - __bfloat162float(hh));
}

__device__ __forceinline__ void split_pack(float f0, float f1,
                                           unsigned &hi, unsigned &lo) {
    bf16 h0 = __float2bfloat16(f0);
    bf16 h1 = __float2bfloat16(f1);
    bf16 l0 = __float2bfloat16(f0 - __bfloat162float(h0));
    bf16 l1 = __float2bfloat16(f1 - __bfloat162float(h1));
    __nv_bfloat162 th; th.x = h0; th.y = h1;
    __nv_bfloat162 tl; tl.x = l0; tl.y = l1;
    hi = *reinterpret_cast<unsigned*>(&th);
    lo = *reinterpret_cast<unsigned*>(&tl);
}

__device__ __forceinline__ unsigned su32(const void* p) {
    return (unsigned)__cvta_generic_to_shared(p);
}

__device__ __forceinline__ void ldsm4(unsigned r[4], unsigned addr) {
    asm volatile("ldmatrix.sync.aligned.m8n8.x4.shared.b16 {%0,%1,%2,%3}, [%4];"
                 : "=r"(r[0]), "=r"(r[1]), "=r"(r[2]), "=r"(r[3]) : "r"(addr));
}
__device__ __forceinline__ void ldsm4t(unsigned r[4], unsigned addr) {
    asm volatile("ldmatrix.sync.aligned.m8n8.x4.trans.shared.b16 {%0,%1,%2,%3}, [%4];"
                 : "=r"(r[0]), "=r"(r[1]), "=r"(r[2]), "=r"(r[3]) : "r"(addr));
}

__device__ __forceinline__ void mma_bf16(float c[4], const unsigned a[4],
                                         const unsigned b[2]) {
    asm volatile(
        "mma.sync.aligned.m16n8k16.row.col.f32.bf16.bf16.f32 "
        "{%0,%1,%2,%3}, {%4,%5,%6,%7}, {%8,%9}, {%0,%1,%2,%3};"
        : "+f"(c[0]), "+f"(c[1]), "+f"(c[2]), "+f"(c[3])
        : "r"(a[0]), "r"(a[1]), "r"(a[2]), "r"(a[3]), "r"(b[0]), "r"(b[1]));
}

// ============================================================================
// Kernel 0: split everything into bf16 hi/lo once.
// ============================================================================
__global__ void prep_split(const float* __restrict__ x,
    const float* __restrict__ Wq, const float* __restrict__ bq,
    const float* __restrict__ Wk, const float* __restrict__ bk,
    const float* __restrict__ Wv, const float* __restrict__ bv,
    const float* __restrict__ Wo)
{
    const int stride = gridDim.x * blockDim.x;
    const int t0 = blockIdx.x * blockDim.x + threadIdx.x;

    for (int i = t0; i < MT*E_; i += stride)
        split1(x[i], &g_xh[i], &g_xl[i]);

    for (int i = t0; i < E_*NQKV; i += stride) {
        int k = i / NQKV, n = i % NQKV;
        int which = n >> 10, h = (n & 1023) >> 6, d = n & 63;
        const float* W = (which == 0) ? Wq : (which == 1) ? Wk : Wv;
        split1(W[((size_t)h*E_ + k)*DH_ + d], &g_Wah[i], &g_Wal[i]);
    }

    for (int i = t0; i < HD*E_; i += stride)
        split1(Wo[i], &g_Woh[i], &g_Wol[i]);

    for (int n = t0; n < NQKV; n += stride) {
        int which = n >> 10, h = (n & 1023) >> 6, d = n & 63;
        const float* bb = (which == 0) ? bq : (which == 1) ? bk : bv;
        g_bias[n] = bb[h*DH_ + d];
    }
}

// ============================================================================
// Kernel 1: QKV projection. C[8192, 3072] = x @ Wall, split-bf16 mma.
//   BM=128, BN=64, BK=32; 256 thr, 8 warps (4m x 2n), warp tile 32x32.
//   Epilogue adds bias, folds softmax scale into q, writes bf16 hi/lo qkv.
// ============================================================================
__global__ __launch_bounds__(256) void gemm_qkv()
{
    __shared__ bf16 Ash[128*40], Asl[128*40];
    __shared__ bf16 Bsh[32*72],  Bsl[32*72];

    const int tid = threadIdx.x, lane = tid & 31, warp = tid >> 5;
    const int wm = warp >> 1, wn = warp & 1;
    const int mBase = blockIdx.y * 128, nBase = blockIdx.x * 64;
    const int which = nBase >> 10, h = (nBase & 1023) >> 6;

    const int a_row = tid >> 1, a_k = (tid & 1) * 16;
    const int b_row = tid >> 3, b_n = (tid & 7) * 8;

    const int aoff = (lane & 15) * 40 + (lane >> 4) * 8;   // A ldmatrix lane offset
    const int boff = (lane & 15) * 72 + (lane >> 4) * 8;   // B ldmatrix lane offset

    float acc[2][4][4];
    #pragma unroll
    for (int i = 0; i < 2; i++)
        #pragma unroll
        for (int j = 0; j < 4; j++)
            #pragma unroll
            for (int t = 0; t < 4; t++) acc[i][j][t] = 0.f;

    for (int k0 = 0; k0 < E_; k0 += 32) {
        *(uint4*)&Ash[a_row*40 + a_k]     = *(const uint4*)&g_xh[(size_t)(mBase+a_row)*E_ + k0 + a_k];
        *(uint4*)&Ash[a_row*40 + a_k + 8] = *(const uint4*)&g_xh[(size_t)(mBase+a_row)*E_ + k0 + a_k + 8];
        *(uint4*)&Asl[a_row*40 + a_k]     = *(const uint4*)&g_xl[(size_t)(mBase+a_row)*E_ + k0 + a_k];
        *(uint4*)&Asl[a_row*40 + a_k + 8] = *(const uint4*)&g_xl[(size_t)(mBase+a_row)*E_ + k0 + a_k + 8];
        *(uint4*)&Bsh[b_row*72 + b_n]     = *(const uint4*)&g_Wah[(size_t)(k0+b_row)*NQKV + nBase + b_n];
        *(uint4*)&Bsl[b_row*72 + b_n]     = *(const uint4*)&g_Wal[(size_t)(k0+b_row)*NQKV + nBase + b_n];
        __syncthreads();

        #pragma unroll
        for (int kh = 0; kh < 2; kh++) {
            unsigned ah[2][4], al[2][4];
            #pragma unroll
            for (int f = 0; f < 2; f++) {
                ldsm4(ah[f], su32(Ash + (wm*32 + f*16)*40 + kh*16 + aoff));
                ldsm4(al[f], su32(Asl + (wm*32 + f*16)*40 + kh*16 + aoff));
            }
            #pragma unroll
            for (int g = 0; g < 2; g++) {
                unsigned th[4], tl[4];
                ldsm4t(th, su32(Bsh + kh*16*72 + wn*32 + g*16 + boff));
                ldsm4t(tl, su32(Bsl + kh*16*72 + wn*32 + g*16 + boff));
                unsigned bh0[2] = {th[0], th[1]}, bh1[2] = {th[2], th[3]};
                unsigned bl0[2] = {tl[0], tl[1]}, bl1[2] = {tl[2], tl[3]};
                #pragma unroll
                for (int i = 0; i < 2; i++) {
                    mma_bf16(acc[i][2*g],   ah[i], bh0);
                    mma_bf16(acc[i][2*g],   ah[i], bl0);
                    mma_bf16(acc[i][2*g],   al[i], bh0);
                    mma_bf16(acc[i][2*g+1], ah[i], bh1);
                    mma_bf16(acc[i][2*g+1], ah[i], bl1);
                    mma_bf16(acc[i][2*g+1], al[i], bh1);
                }
            }
        }
        __syncthreads();
    }

    bf16* oh = (which == 0) ? g_qh : (which == 1) ? g_kh : g_vh;
    bf16* ol = (which == 0) ? g_ql : (which == 1) ? g_kl : g_vl;
    const float scl = (which == 0) ? 0.125f : 1.0f;

    #pragma unroll
    for (int i = 0; i < 2; i++) {
        #pragma unroll
        for (int j = 0; j < 4; j++) {
            int d  = wn*32 + j*8 + (lane & 3)*2;
            float b0 = g_bias[nBase + d], b1 = g_bias[nBase + d + 1];
            int r = mBase + wm*32 + i*16 + (lane >> 2);
            #pragma unroll
            for (int t = 0; t < 2; t++) {
                int rr = r + t*8;
                int bb = rr >> 11, s = rr & 2047;
                size_t ad = ((size_t)(bb*H_ + h)*S_ + s)*DH_ + d;
                float f0 = (acc[i][j][t*2+0] + b0) * scl;
                float f1 = (acc[i][j][t*2+1] + b1) * scl;
                unsigned ph, pl;
                split_pack(f0, f1, ph, pl);
                *(unsigned*)&oh[ad] = ph;
                *(unsigned*)&ol[ad] = pl;
            }
        }
    }
}

// ============================================================================
// Kernel 2: flash attention, split-bf16 mma. 128 thr (4 warps x 16 q-rows),
//   BM=64 queries, BN=64 keys per tile, online softmax, P register-resident.
// ============================================================================
__global__ __launch_bounds__(128) void attn()
{
    __shared__ bf16 Ksh[64*72], Ksl[64*72], Vsh[64*72], Vsl[64*72];

    const int tid = threadIdx.x, lane = tid & 31, warp = tid >> 5;
    const int bh = blockIdx.y, qBase = blockIdx.x * 64;

    const bf16* kh_p = g_kh + (size_t)bh*S_*DH_;
    const bf16* kl_p = g_kl + (size_t)bh*S_*DH_;
    const bf16* vh_p = g_vh + (size_t)bh*S_*DH_;
    const bf16* vl_p = g_vl + (size_t)bh*S_*DH_;

    // Q fragments direct from gmem (already scaled by 0.125 in K1)
    unsigned aqh[4][4], aql[4][4];
    {
        const bf16* qh_p = g_qh + (size_t)bh*S_*DH_;
        const bf16* ql_p = g_ql + (size_t)bh*S_*DH_;
        int r0 = qBase + warp*16 + (lane >> 2);
        #pragma unroll
        for (int kc = 0; kc < 4; kc++) {
            int c = kc*16 + (lane & 3)*2;
            aqh[kc][0] = *(const unsigned*)&qh_p[(size_t)r0*DH_ + c];
            aqh[kc][1] = *(const unsigned*)&qh_p[(size_t)(r0+8)*DH_ + c];
            aqh[kc][2] = *(const unsigned*)&qh_p[(size_t)r0*DH_ + c + 8];
            aqh[kc][3] = *(const unsigned*)&qh_p[(size_t)(r0+8)*DH_ + c + 8];
            aql[kc][0] = *(const unsigned*)&ql_p[(size_t)r0*DH_ + c];
            aql[kc][1] = *(const unsigned*)&ql_p[(size_t)(r0+8)*DH_ + c];
            aql[kc][2] = *(const unsigned*)&ql_p[(size_t)r0*DH_ + c + 8];
            aql[kc][3] = *(const unsigned*)&ql_p[(size_t)(r0+8)*DH_ + c + 8];
        }
    }

    float oacc[8][4];
    #pragma unroll
    for (int j = 0; j < 8; j++)
        #pragma unroll
        for (int t = 0; t < 4; t++) oacc[j][t] = 0.f;
    float m0 = -3.0e38f, m1 = -3.0e38f, l0 = 0.f, l1 = 0.f;

    for (int kt = 0; kt < S_/64; kt++) {
        __syncthreads();
        const int kbase = kt * 64;
        #pragma unroll
        for (int p = 0; p < 4; p++) {
            int li = p*128 + tid;
            int row = li >> 3, c8 = (li & 7)*8;
            *(uint4*)&Ksh[row*72 + c8] = *(const uint4*)&kh_p[(size_t)(kbase+row)*DH_ + c8];
            *(uint4*)&Ksl[row*72 + c8] = *(const uint4*)&kl_p[(size_t)(kbase+row)*DH_ + c8];
            *(uint4*)&Vsh[row*72 + c8] = *(const uint4*)&vh_p[(size_t)(kbase+row)*DH_ + c8];
            *(uint4*)&Vsl[row*72 + c8] = *(const uint4*)&vl_p[(size_t)(kbase+row)*DH_ + c8];
        }
        __syncthreads();

        // ---- GEMM1: scores = Q K^T ----
        float sacc[8][4];
        #pragma unroll
        for (int j = 0; j < 8; j++)
            #pragma unroll
            for (int t = 0; t < 4; t++) sacc[j][t] = 0.f;

        #pragma unroll
        for (int kc = 0; kc < 4; kc++) {
            #pragma unroll
            for (int g = 0; g < 4; g++) {
                // non-trans: rows=keys, cols=d
                int off = (g*16 + (lane >> 4)*8 + (lane & 7))*72 + kc*16 + ((lane >> 3) & 1)*8;
                unsigned th[4], tl[4];
                ldsm4(th, su32(Ksh + off));
                ldsm4(tl, su32(Ksl + off));
                unsigned bh0[2] = {th[0], th[1]}, bh1[2] = {th[2], th[3]};
                unsigned bl0[2] = {tl[0], tl[1]}, bl1[2] = {tl[2], tl[3]};
                mma_bf16(sacc[2*g],   aqh[kc], bh0);
                mma_bf16(sacc[2*g],   aqh[kc], bl0);
                mma_bf16(sacc[2*g],   aql[kc], bh0);
                mma_bf16(sacc[2*g+1], aqh[kc], bh1);
                mma_bf16(sacc[2*g+1], aqh[kc], bl1);
                mma_bf16(sacc[2*g+1], aql[kc], bh1);
            }
        }

        // ---- online softmax (rows l>>2 and l>>2 + 8) ----
        float rmax0 = -3.0e38f, rmax1 = -3.0e38f;
        #pragma unroll
        for (int j = 0; j < 8; j++) {
            rmax0 = fmaxf(rmax0, fmaxf(sacc[j][0], sacc[j][1]));
            rmax1 = fmaxf(rmax1, fmaxf(sacc[j][2], sacc[j][3]));
        }
        rmax0 = fmaxf(rmax0, __shfl_xor_sync(0xffffffffu, rmax0, 1));
        rmax0 = fmaxf(rmax0, __shfl_xor_sync(0xffffffffu, rmax0, 2));
        rmax1 = fmaxf(rmax1, __shfl_xor_sync(0xffffffffu, rmax1, 1));
        rmax1 = fmaxf(rmax1, __shfl_xor_sync(0xffffffffu, rmax1, 2));
        float mn0 = fmaxf(m0, rmax0), mn1 = fmaxf(m1, rmax1);
        float c0 = __expf(m0 - mn0), c1 = __expf(m1 - mn1);
        m0 = mn0; m1 = mn1;
        float rs0 = 0.f, rs1 = 0.f;
        #pragma unroll
        for (int j = 0; j < 8; j++) {
            sacc[j][0] = __expf(sacc[j][0] - mn0);
            sacc[j][1] = __expf(sacc[j][1] - mn0);
            sacc[j][2] = __expf(sacc[j][2] - mn1);
            sacc[j][3] = __expf(sacc[j][3] - mn1);
            rs0 += sacc[j][0] + sacc[j][1];
            rs1 += sacc[j][2] + sacc[j][3];
        }
        rs0 += __shfl_xor_sync(0xffffffffu, rs0, 1);
        rs0 += __shfl_xor_sync(0xffffffffu, rs0, 2);
        rs1 += __shfl_xor_sync(0xffffffffu, rs1, 1);
        rs1 += __shfl_xor_sync(0xffffffffu, rs1, 2);
        l0 = l0*c0 + rs0;
        l1 = l1*c1 + rs1;
        #pragma unroll
        for (int j = 0; j < 8; j++) {
            oacc[j][0] *= c0; oacc[j][1] *= c0;
            oacc[j][2] *= c1; oacc[j][3] *= c1;
        }

        // ---- GEMM2: O += P V ----
        #pragma unroll
        for (int kc2 = 0; kc2 < 4; kc2++) {
            unsigned aph[4], apl[4];
            split_pack(sacc[2*kc2][0],   sacc[2*kc2][1],   aph[0], apl[0]);
            split_pack(sacc[2*kc2][2],   sacc[2*kc2][3],   aph[1], apl[1]);
            split_pack(sacc[2*kc2+1][0], sacc[2*kc2+1][1], aph[2], apl[2]);
            split_pack(sacc[2*kc2+1][2], sacc[2*kc2+1][3], aph[3], apl[3]);
            #pragma unroll
            for (int g2 = 0; g2 < 4; g2++) {
                int off = (kc2*16 + (lane & 15))*72 + g2*16 + (lane >> 4)*8;
                unsigned th[4], tl[4];
                ldsm4t(th, su32(Vsh + off));
                ldsm4t(tl, su32(Vsl + off));
                unsigned bh0[2] = {th[0], th[1]}, bh1[2] = {th[2], th[3]};
                unsigned bl0[2] = {tl[0], tl[1]}, bl1[2] = {tl[2], tl[3]};
                mma_bf16(oacc[2*g2],   aph, bh0);
                mma_bf16(oacc[2*g2],   aph, bl0);
                mma_bf16(oacc[2*g2],   apl, bh0);
                mma_bf16(oacc[2*g2+1], aph, bh1);
                mma_bf16(oacc[2*g2+1], aph, bl1);
                mma_bf16(oacc[2*g2+1], apl, bh1);
            }
        }
    }

    // ---- epilogue: z[b][s][h*64+d] as bf16 hi/lo ----
    float inv0 = 1.0f / l0, inv1 = 1.0f / l1;
    const int bb = bh >> 4, hh = bh & 15;
    const int r = qBase + warp*16 + (lane >> 2);
    #pragma unroll
    for (int j = 0; j < 8; j++) {
        int d = hh*DH_ + j*8 + (lane & 3)*2;
        size_t a0 = ((size_t)(bb*S_ + r))*HD + d;
        size_t a1 = ((size_t)(bb*S_ + r + 8))*HD + d;
        unsigned ph, pl;
        split_pack(oacc[j][0]*inv0, oacc[j][1]*inv0, ph, pl);
        *(unsigned*)&g_zh[a0] = ph; *(unsigned*)&g_zl[a0] = pl;
        split_pack(oacc[j][2]*inv1, oacc[j][3]*inv1, ph, pl);
        *(unsigned*)&g_zh[a1] = ph; *(unsigned*)&g_zl[a1] = pl;
    }
}

// ============================================================================
// Kernel 3: out = z @ Wo + bo. Same tiling as K1, fp32 output.
// ============================================================================
__global__ __launch_bounds__(256) void gemm_out(const float* __restrict__ bo,
                                                float* __restrict__ out)
{
    __shared__ bf16 Ash[128*40], Asl[128*40];
    __shared__ bf16 Bsh[32*72],  Bsl[32*72];

    const int tid = threadIdx.x, lane = tid & 31, warp = tid >> 5;
    const int wm = warp >> 1, wn = warp & 1;
    const int mBase = blockIdx.y * 128, nBase = blockIdx.x * 64;

    const int a_row = tid >> 1, a_k = (tid & 1) * 16;
    const int b_row = tid >> 3, b_n = (tid & 7) * 8;
    const int aoff = (lane & 15) * 40 + (lane >> 4) * 8;
    const int boff = (lane & 15) * 72 + (lane >> 4) * 8;

    float acc[2][4][4];
    #pragma unroll
    for (int i = 0; i < 2; i++)
        #pragma unroll
        for (int j = 0; j < 4; j++)
            #pragma unroll
            for (int t = 0; t < 4; t++) acc[i][j][t] = 0.f;

    for (int k0 = 0; k0 < HD; k0 += 32) {
        *(uint4*)&Ash[a_row*40 + a_k]     = *(const uint4*)&g_zh[(size_t)(mBase+a_row)*HD + k0 + a_k];
        *(uint4*)&Ash[a_row*40 + a_k + 8] = *(const uint4*)&g_zh[(size_t)(mBase+a_row)*HD + k0 + a_k + 8];
        *(uint4*)&Asl[a_row*40 + a_k]     = *(const uint4*)&g_zl[(size_t)(mBase+a_row)*HD + k0 + a_k];
        *(uint4*)&Asl[a_row*40 + a_k + 8] = *(const uint4*)&g_zl[(size_t)(mBase+a_row)*HD + k0 + a_k + 8];
        *(uint4*)&Bsh[b_row*72 + b_n]     = *(const uint4*)&g_Woh[(size_t)(k0+b_row)*E_ + nBase + b_n];
        *(uint4*)&Bsl[b_row*72 + b_n]     = *(const uint4*)&g_Wol[(size_t)(k0+b_row)*E_ + nBase + b_n];
        __syncthreads();

        #pragma unroll
        for (int kh = 0; kh < 2; kh++) {
            unsigned ah[2][4], al[2][4];
            #pragma unroll
            for (int f = 0; f < 2; f++) {
                ldsm4(ah[f], su32(Ash + (wm*32 + f*16)*40 + kh*16 + aoff));
                ldsm4(al[f], su32(Asl + (wm*32 + f*16)*40 + kh*16 + aoff));
            }
            #pragma unroll
            for (int g = 0; g < 2; g++) {
                unsigned th[4], tl[4];
                ldsm4t(th, su32(Bsh + kh*16*72 + wn*32 + g*16 + boff));
                ldsm4t(tl, su32(Bsl + kh*16*72 + wn*32 + g*16 + boff));
                unsigned bh0[2] = {th[0], th[1]}, bh1[2] = {th[2], th[3]};
                unsigned bl0[2] = {tl[0], tl[1]}, bl1[2] = {tl[2], tl[3]};
                #pragma unroll
                for (int i = 0; i < 2; i++) {
                    mma_bf16(acc[i][2*g],   ah[i], bh0);
                    mma_bf16(acc[i][2*g],   ah[i], bl0);
                    mma_bf16(acc[i][2*g],   al[i], bh0);
                    mma_bf16(acc[i][2*g+1], ah[i], bh1);
                    mma_bf16(acc[i][2*g+1], ah[i], bl1);
                    mma_bf16(acc[i][2*g+1], al[i], bh1);
                }
            }
        }
        __syncthreads();
    }

    #pragma unroll
    for (int i = 0; i < 2; i++) {
        #pragma unroll
        for (int j = 0; j < 4; j++) {
            int n0 = nBase + wn*32 + j*8 + (lane & 3)*2;
            float b0 = bo[n0], b1 = bo[n0 + 1];
            int r = mBase + wm*32 + i*16 + (lane >> 2);
            #pragma unroll
            for (int t = 0; t < 2; t++) {
                int rr = r + t*8;
                float2 v;
                v.x = acc[i][j][t*2+0] + b0;
                v.y = acc[i][j][t*2+1] + b1;
                *(float2*)&out[(size_t)rr*E_ + n0] = v;
            }
        }
    }
}

// ============================================================================
// Launch
// ============================================================================
extern "C" void kernel_launch(void* const* d_in, const int* in_sizes, int n_in,
                              void* d_out, int out_size)
{
    const float* x  = (const float*)d_in[0];
    const float* Wq = (const float*)d_in[1];
    const float* bq = (const float*)d_in[2];
    const float* Wk = (const float*)d_in[3];
    const float* bk = (const float*)d_in[4];
    const float* Wv = (const float*)d_in[5];
    const float* bv = (const float*)d_in[6];
    const float* Wo = (const float*)d_in[7];
    const float* bo = (const float*)d_in[8];
    float* out = (float*)d_out;

    prep_split<<<4096, 256>>>(x, Wq, bq, Wk, bk, Wv, bv, Wo);
    gemm_qkv<<<dim3(NQKV/64, MT/128), 256>>>();
    attn<<<dim3(S_/64, B_*H_), 128>>>();
    gemm_out<<<dim3(E_/64, MT/128), 256>>>(bo, out);
}

// round 9
// speedup vs baseline: 2.7678x; 1.8072x over previous
#include <cuda_runtime.h>
#include <cuda_bf16.h>
#include <math.h>
#include <stdint.h>

#define B_    4
#define S_    2048
#define E_    1024
#define H_    16
#define DH_   64
#define MT    (B_*S_)        // 8192 tokens
#define HD    (H_*DH_)       // 1024
#define NQKV  (3*HD)         // 3072

typedef __nv_bfloat16 bf16;

// ---------------- split scratch buffers (device globals) --------------------
__device__ bf16 g_xh[MT*E_],  g_xl[MT*E_];          // x   [m][k]
__device__ bf16 g_Wah[E_*NQKV], g_Wal[E_*NQKV];     // QKV weights [k][n]
__device__ bf16 g_Woh[HD*E_], g_Wol[HD*E_];         // Wo  [k][n]
__device__ float g_bias[NQKV];
__device__ bf16 g_qh[B_*H_*S_*DH_], g_ql[B_*H_*S_*DH_];
__device__ bf16 g_kh[B_*H_*S_*DH_], g_kl[B_*H_*S_*DH_];
__device__ bf16 g_vh[B_*H_*S_*DH_], g_vl[B_*H_*S_*DH_];
__device__ bf16 g_zh[MT*HD],  g_zl[MT*HD];          // z   [m][k]

// ---------------- helpers ---------------------------------------------------
__device__ __forceinline__ void split1(float v, bf16* h, bf16* l) {
    bf16 hh = __float2bfloat16(v);
    *h = hh;
    *l = __float2bfloat16(v - __bfloat162float(hh));
}

__device__ __forceinline__ void split_pack(float f0, float f1,
                                           unsigned &hi, unsigned &lo) {
    bf16 h0 = __float2bfloat16(f0);
    bf16 h1 = __float2bfloat16(f1);
    bf16 l0 = __float2bfloat16(f0 - __bfloat162float(h0));
    bf16 l1 = __float2bfloat16(f1 - __bfloat162float(h1));
    __nv_bfloat162 th; th.x = h0; th.y = h1;
    __nv_bfloat162 tl; tl.x = l0; tl.y = l1;
    hi = *reinterpret_cast<unsigned*>(&th);
    lo = *reinterpret_cast<unsigned*>(&tl);
}

__device__ __forceinline__ unsigned su32(const void* p) {
    return (unsigned)__cvta_generic_to_shared(p);
}

__device__ __forceinline__ void ldsm4(unsigned r[4], unsigned addr) {
    asm volatile("ldmatrix.sync.aligned.m8n8.x4.shared.b16 {%0,%1,%2,%3}, [%4];"
                 : "=r"(r[0]), "=r"(r[1]), "=r"(r[2]), "=r"(r[3]) : "r"(addr));
}
__device__ __forceinline__ void ldsm4t(unsigned r[4], unsigned addr) {
    asm volatile("ldmatrix.sync.aligned.m8n8.x4.trans.shared.b16 {%0,%1,%2,%3}, [%4];"
                 : "=r"(r[0]), "=r"(r[1]), "=r"(r[2]), "=r"(r[3]) : "r"(addr));
}
__device__ __forceinline__ void mma_bf16(float c[4], const unsigned a[4],
                                         const unsigned b[2]) {
    asm volatile(
        "mma.sync.aligned.m16n8k16.row.col.f32.bf16.bf16.f32 "
        "{%0,%1,%2,%3}, {%4,%5,%6,%7}, {%8,%9}, {%0,%1,%2,%3};"
        : "+f"(c[0]), "+f"(c[1]), "+f"(c[2]), "+f"(c[3])
        : "r"(a[0]), "r"(a[1]), "r"(a[2]), "r"(a[3]), "r"(b[0]), "r"(b[1]));
}

#define CP16(dst, src) \
    asm volatile("cp.async.cg.shared.global [%0], [%1], 16;" \
                 :: "r"(dst), "l"(src) : "memory")
#define CP_COMMIT()  asm volatile("cp.async.commit_group;" ::: "memory")
#define CP_WAIT1()   asm volatile("cp.async.wait_group 1;" ::: "memory")
#define CP_WAIT0()   asm volatile("cp.async.wait_group 0;" ::: "memory")

// ============================================================================
// Kernel 0: split everything into bf16 hi/lo once (weights as [k][n])
// ============================================================================
__global__ void prep_split(const float* __restrict__ x,
    const float* __restrict__ Wq, const float* __restrict__ bq,
    const float* __restrict__ Wk, const float* __restrict__ bk,
    const float* __restrict__ Wv, const float* __restrict__ bv,
    const float* __restrict__ Wo)
{
    const int stride = gridDim.x * blockDim.x;
    const int t0 = blockIdx.x * blockDim.x + threadIdx.x;

    for (int i = t0; i < MT*E_; i += stride)
        split1(x[i], &g_xh[i], &g_xl[i]);

    for (int i = t0; i < E_*NQKV; i += stride) {
        int k = i / NQKV, n = i % NQKV;
        int which = n >> 10, h = (n & 1023) >> 6, d = n & 63;
        const float* W = (which == 0) ? Wq : (which == 1) ? Wk : Wv;
        split1(W[((size_t)h*E_ + k)*DH_ + d], &g_Wah[i], &g_Wal[i]);
    }

    for (int i = t0; i < HD*E_; i += stride)
        split1(Wo[i], &g_Woh[i], &g_Wol[i]);

    for (int n = t0; n < NQKV; n += stride) {
        int which = n >> 10, h = (n & 1023) >> 6, d = n & 63;
        const float* bb = (which == 0) ? bq : (which == 1) ? bk : bv;
        g_bias[n] = bb[h*DH_ + d];
    }
}

// ============================================================================
// GEMM core: C[128,128] per block = A[128,1024] @ B[1024,128], split-bf16.
// 256 thr, 8 warps (wm=warp&3 row 32-strip, wn=warp>>2 col 64-strip).
// Double-buffered cp.async, BK=32.
// smem buffer (elements): Ah[128*40] Al[128*40] Bh[32*136] Bl[32*136] = 18944
// ============================================================================
#define GBUF 18944
#define GEMM_SMEM_BYTES (2*GBUF*2)   // 75776 bytes

__device__ __forceinline__ void gemm_loadtile(bf16* sm,
    const bf16* Ah, const bf16* Al, const bf16* Bh, const bf16* Bl,
    int ldb, int mBase, int nBase, int k0, int tid)
{
    bf16* Ash = sm;            bf16* Asl = sm + 5120;
    bf16* Bsh = sm + 10240;    bf16* Bsl = sm + 14592;
    #pragma unroll
    for (int t = 0; t < 2; t++) {
        int idx = t*256 + tid;
        int ar = idx >> 2, as = idx & 3;
        size_t ga = (size_t)(mBase + ar)*E_ + k0 + as*8;
        CP16(su32(Ash + ar*40 + as*8), Ah + ga);
        CP16(su32(Asl + ar*40 + as*8), Al + ga);
        int br = idx >> 4, bs = idx & 15;
        size_t gb = (size_t)(k0 + br)*ldb + nBase + bs*8;
        CP16(su32(Bsh + br*136 + bs*8), Bh + gb);
        CP16(su32(Bsl + br*136 + bs*8), Bl + gb);
    }
    CP_COMMIT();
}

__device__ __forceinline__ void gemm_compute(const bf16* sm, float acc[2][8][4],
                                             int wm, int wn, int lane)
{
    const bf16* Ash = sm;            const bf16* Asl = sm + 5120;
    const bf16* Bsh = sm + 10240;    const bf16* Bsl = sm + 14592;
    const int aoff = (lane & 15)*40 + (lane >> 4)*8;
    const int boff = (lane & 15)*136 + (lane >> 4)*8;

    #pragma unroll
    for (int kh = 0; kh < 2; kh++) {
        unsigned ah[2][4], al[2][4];
        #pragma unroll
        for (int f = 0; f < 2; f++) {
            ldsm4(ah[f], su32(Ash + (wm*32 + f*16)*40 + kh*16 + aoff));
            ldsm4(al[f], su32(Asl + (wm*32 + f*16)*40 + kh*16 + aoff));
        }
        #pragma unroll
        for (int g = 0; g < 4; g++) {
            unsigned th[4], tl[4];
            ldsm4t(th, su32(Bsh + kh*16*136 + wn*64 + g*16 + boff));
            ldsm4t(tl, su32(Bsl + kh*16*136 + wn*64 + g*16 + boff));
            unsigned bh0[2] = {th[0], th[1]}, bh1[2] = {th[2], th[3]};
            unsigned bl0[2] = {tl[0], tl[1]}, bl1[2] = {tl[2], tl[3]};
            #pragma unroll
            for (int i = 0; i < 2; i++) {
                mma_bf16(acc[i][2*g],   ah[i], bh0);
                mma_bf16(acc[i][2*g],   ah[i], bl0);
                mma_bf16(acc[i][2*g],   al[i], bh0);
                mma_bf16(acc[i][2*g+1], ah[i], bh1);
                mma_bf16(acc[i][2*g+1], ah[i], bl1);
                mma_bf16(acc[i][2*g+1], al[i], bh1);
            }
        }
    }
}

__device__ __forceinline__ void gemm_main(
    const bf16* Ah, const bf16* Al, const bf16* Bh, const bf16* Bl,
    int ldb, int mBase, int nBase, float acc[2][8][4])
{
    extern __shared__ __align__(16) bf16 dynsm[];
    const int tid = threadIdx.x;
    const int lane = tid & 31, warp = tid >> 5;
    const int wm = warp & 3, wn = warp >> 2;

    #pragma unroll
    for (int i = 0; i < 2; i++)
        #pragma unroll
        for (int j = 0; j < 8; j++)
            #pragma unroll
            for (int t = 0; t < 4; t++) acc[i][j][t] = 0.f;

    gemm_loadtile(dynsm, Ah, Al, Bh, Bl, ldb, mBase, nBase, 0, tid);

    for (int it = 0; it < 32; it++) {
        if (it + 1 < 32)
            gemm_loadtile(dynsm + ((it+1) & 1)*GBUF, Ah, Al, Bh, Bl,
                          ldb, mBase, nBase, (it+1)*32, tid);
        if (it + 1 < 32) { CP_WAIT1(); } else { CP_WAIT0(); }
        __syncthreads();
        gemm_compute(dynsm + (it & 1)*GBUF, acc, wm, wn, lane);
        __syncthreads();
    }
}

// ============================================================================
// Kernel 1: QKV projection. grid (3072/128, 8192/128) = (24, 64)
// ============================================================================
__global__ __launch_bounds__(256) void gemm_qkv2()
{
    const int tid = threadIdx.x, lane = tid & 31, warp = tid >> 5;
    const int wm = warp & 3, wn = warp >> 2;
    const int mBase = blockIdx.y * 128, nBase = blockIdx.x * 128;

    float acc[2][8][4];
    gemm_main(g_xh, g_xl, g_Wah, g_Wal, NQKV, mBase, nBase, acc);

    const int colbase = nBase + wn*64;
    const int which = colbase >> 10;
    const int h = (colbase & 1023) >> 6;
    bf16* oh = (which == 0) ? g_qh : (which == 1) ? g_kh : g_vh;
    bf16* ol = (which == 0) ? g_ql : (which == 1) ? g_kl : g_vl;
    const float scl = (which == 0) ? 0.125f : 1.0f;

    #pragma unroll
    for (int i = 0; i < 2; i++) {
        #pragma unroll
        for (int t = 0; t < 2; t++) {
            int m = mBase + wm*32 + i*16 + (lane >> 2) + t*8;
            int bb = m >> 11, s = m & 2047;
            size_t rowoff = ((size_t)(bb*H_ + h)*S_ + s)*DH_;
            #pragma unroll
            for (int j = 0; j < 8; j++) {
                int d = j*8 + (lane & 3)*2;
                float f0 = (acc[i][j][t*2+0] + g_bias[colbase + d])     * scl;
                float f1 = (acc[i][j][t*2+1] + g_bias[colbase + d + 1]) * scl;
                unsigned ph, pl;
                split_pack(f0, f1, ph, pl);
                *(unsigned*)&oh[rowoff + d] = ph;
                *(unsigned*)&ol[rowoff + d] = pl;
            }
        }
    }
}

// ============================================================================
// Kernel 3: out = z @ Wo + bo. grid (1024/128, 8192/128) = (8, 64)
// ============================================================================
__global__ __launch_bounds__(256) void gemm_out2(const float* __restrict__ bo,
                                                 float* __restrict__ out)
{
    const int tid = threadIdx.x, lane = tid & 31, warp = tid >> 5;
    const int wm = warp & 3, wn = warp >> 2;
    const int mBase = blockIdx.y * 128, nBase = blockIdx.x * 128;

    float acc[2][8][4];
    gemm_main(g_zh, g_zl, g_Woh, g_Wol, E_, mBase, nBase, acc);

    const int colbase = nBase + wn*64;
    #pragma unroll
    for (int i = 0; i < 2; i++) {
        #pragma unroll
        for (int t = 0; t < 2; t++) {
            int m = mBase + wm*32 + i*16 + (lane >> 2) + t*8;
            #pragma unroll
            for (int j = 0; j < 8; j++) {
                int col = colbase + j*8 + (lane & 3)*2;
                float2 v;
                v.x = acc[i][j][t*2+0] + bo[col];
                v.y = acc[i][j][t*2+1] + bo[col + 1];
                *(float2*)&out[(size_t)m*E_ + col] = v;
            }
        }
    }
}

// ============================================================================
// Kernel 2: flash attention, 256 thr / 8 warps, BM=128 q rows, BN=64 keys,
// double-buffered cp.async K/V tiles.
// smem buffer (elements): Kh[64*72] Kl[64*72] Vh[64*72] Vl[64*72] = 18432
// ============================================================================
#define ABUF 18432
#define ATTN_SMEM_BYTES (2*ABUF*2)   // 73728 bytes

__device__ __forceinline__ void attn_loadtile(bf16* sm,
    const bf16* kh_p, const bf16* kl_p, const bf16* vh_p, const bf16* vl_p,
    int kbase, int tid)
{
    bf16* Ksh = sm;           bf16* Ksl = sm + 4608;
    bf16* Vsh = sm + 9216;    bf16* Vsl = sm + 13824;
    #pragma unroll
    for (int t = 0; t < 2; t++) {
        int idx = t*256 + tid;
        int row = idx >> 3, seg = idx & 7;
        size_t g = (size_t)(kbase + row)*DH_ + seg*8;
        int so = row*72 + seg*8;
        CP16(su32(Ksh + so), kh_p + g);
        CP16(su32(Ksl + so), kl_p + g);
        CP16(su32(Vsh + so), vh_p + g);
        CP16(su32(Vsl + so), vl_p + g);
    }
    CP_COMMIT();
}

__global__ __launch_bounds__(256) void attn2()
{
    extern __shared__ __align__(16) bf16 dynsm[];
    const int tid = threadIdx.x, lane = tid & 31, warp = tid >> 5;
    const int bh = blockIdx.y, qBase = blockIdx.x * 128;

    const bf16* kh_p = g_kh + (size_t)bh*S_*DH_;
    const bf16* kl_p = g_kl + (size_t)bh*S_*DH_;
    const bf16* vh_p = g_vh + (size_t)bh*S_*DH_;
    const bf16* vl_p = g_vl + (size_t)bh*S_*DH_;

    // Q fragments direct from gmem (pre-scaled by 0.125 in K1)
    unsigned aqh[4][4], aql[4][4];
    {
        const bf16* qh_p = g_qh + (size_t)bh*S_*DH_;
        const bf16* ql_p = g_ql + (size_t)bh*S_*DH_;
        int r0 = qBase + warp*16 + (lane >> 2);
        #pragma unroll
        for (int kc = 0; kc < 4; kc++) {
            int c = kc*16 + (lane & 3)*2;
            aqh[kc][0] = *(const unsigned*)&qh_p[(size_t)r0*DH_ + c];
            aqh[kc][1] = *(const unsigned*)&qh_p[(size_t)(r0+8)*DH_ + c];
            aqh[kc][2] = *(const unsigned*)&qh_p[(size_t)r0*DH_ + c + 8];
            aqh[kc][3] = *(const unsigned*)&qh_p[(size_t)(r0+8)*DH_ + c + 8];
            aql[kc][0] = *(const unsigned*)&ql_p[(size_t)r0*DH_ + c];
            aql[kc][1] = *(const unsigned*)&ql_p[(size_t)(r0+8)*DH_ + c];
            aql[kc][2] = *(const unsigned*)&ql_p[(size_t)r0*DH_ + c + 8];
            aql[kc][3] = *(const unsigned*)&ql_p[(size_t)(r0+8)*DH_ + c + 8];
        }
    }

    float oacc[8][4];
    #pragma unroll
    for (int j = 0; j < 8; j++)
        #pragma unroll
        for (int t = 0; t < 4; t++) oacc[j][t] = 0.f;
    float m0 = -3.0e38f, m1 = -3.0e38f, l0 = 0.f, l1 = 0.f;

    attn_loadtile(dynsm, kh_p, kl_p, vh_p, vl_p, 0, tid);

    for (int kt = 0; kt < S_/64; kt++) {
        if (kt + 1 < S_/64)
            attn_loadtile(dynsm + ((kt+1) & 1)*ABUF, kh_p, kl_p, vh_p, vl_p,
                          (kt+1)*64, tid);
        if (kt + 1 < S_/64) { CP_WAIT1(); } else { CP_WAIT0(); }
        __syncthreads();

        const bf16* Ksh = dynsm + (kt & 1)*ABUF;
        const bf16* Ksl = Ksh + 4608;
        const bf16* Vsh = Ksh + 9216;
        const bf16* Vsl = Ksh + 13824;

        // ---- GEMM1: scores = Q K^T ----
        float sacc[8][4];
        #pragma unroll
        for (int j = 0; j < 8; j++)
            #pragma unroll
            for (int t = 0; t < 4; t++) sacc[j][t] = 0.f;

        #pragma unroll
        for (int kc = 0; kc < 4; kc++) {
            #pragma unroll
            for (int g = 0; g < 4; g++) {
                int off = (g*16 + (lane >> 4)*8 + (lane & 7))*72
                        + kc*16 + ((lane >> 3) & 1)*8;
                unsigned th[4], tl[4];
                ldsm4(th, su32(Ksh + off));
                ldsm4(tl, su32(Ksl + off));
                unsigned bh0[2] = {th[0], th[1]}, bh1[2] = {th[2], th[3]};
                unsigned bl0[2] = {tl[0], tl[1]}, bl1[2] = {tl[2], tl[3]};
                mma_bf16(sacc[2*g],   aqh[kc], bh0);
                mma_bf16(sacc[2*g],   aqh[kc], bl0);
                mma_bf16(sacc[2*g],   aql[kc], bh0);
                mma_bf16(sacc[2*g+1], aqh[kc], bh1);
                mma_bf16(sacc[2*g+1], aqh[kc], bl1);
                mma_bf16(sacc[2*g+1], aql[kc], bh1);
            }
        }

        // ---- online softmax ----
        float rmax0 = -3.0e38f, rmax1 = -3.0e38f;
        #pragma unroll
        for (int j = 0; j < 8; j++) {
            rmax0 = fmaxf(rmax0, fmaxf(sacc[j][0], sacc[j][1]));
            rmax1 = fmaxf(rmax1, fmaxf(sacc[j][2], sacc[j][3]));
        }
        rmax0 = fmaxf(rmax0, __shfl_xor_sync(0xffffffffu, rmax0, 1));
        rmax0 = fmaxf(rmax0, __shfl_xor_sync(0xffffffffu, rmax0, 2));
        rmax1 = fmaxf(rmax1, __shfl_xor_sync(0xffffffffu, rmax1, 1));
        rmax1 = fmaxf(rmax1, __shfl_xor_sync(0xffffffffu, rmax1, 2));
        float mn0 = fmaxf(m0, rmax0), mn1 = fmaxf(m1, rmax1);
        float c0 = __expf(m0 - mn0), c1 = __expf(m1 - mn1);
        m0 = mn0; m1 = mn1;
        float rs0 = 0.f, rs1 = 0.f;
        #pragma unroll
        for (int j = 0; j < 8; j++) {
            sacc[j][0] = __expf(sacc[j][0] - mn0);
            sacc[j][1] = __expf(sacc[j][1] - mn0);
            sacc[j][2] = __expf(sacc[j][2] - mn1);
            sacc[j][3] = __expf(sacc[j][3] - mn1);
            rs0 += sacc[j][0] + sacc[j][1];
            rs1 += sacc[j][2] + sacc[j][3];
        }
        rs0 += __shfl_xor_sync(0xffffffffu, rs0, 1);
        rs0 += __shfl_xor_sync(0xffffffffu, rs0, 2);
        rs1 += __shfl_xor_sync(0xffffffffu, rs1, 1);
        rs1 += __shfl_xor_sync(0xffffffffu, rs1, 2);
        l0 = l0*c0 + rs0;
        l1 = l1*c1 + rs1;
        #pragma unroll
        for (int j = 0; j < 8; j++) {
            oacc[j][0] *= c0; oacc[j][1] *= c0;
            oacc[j][2] *= c1; oacc[j][3] *= c1;
        }

        // ---- GEMM2: O += P V ----
        #pragma unroll
        for (int kc2 = 0; kc2 < 4; kc2++) {
            unsigned aph[4], apl[4];
            split_pack(sacc[2*kc2][0],   sacc[2*kc2][1],   aph[0], apl[0]);
            split_pack(sacc[2*kc2][2],   sacc[2*kc2][3],   aph[1], apl[1]);
            split_pack(sacc[2*kc2+1][0], sacc[2*kc2+1][1], aph[2], apl[2]);
            split_pack(sacc[2*kc2+1][2], sacc[2*kc2+1][3], aph[3], apl[3]);
            #pragma unroll
            for (int g2 = 0; g2 < 4; g2++) {
                int off = (kc2*16 + (lane & 15))*72 + g2*16 + (lane >> 4)*8;
                unsigned th[4], tl[4];
                ldsm4t(th, su32(Vsh + off));
                ldsm4t(tl, su32(Vsl + off));
                unsigned bh0[2] = {th[0], th[1]}, bh1[2] = {th[2], th[3]};
                unsigned bl0[2] = {tl[0], tl[1]}, bl1[2] = {tl[2], tl[3]};
                mma_bf16(oacc[2*g2],   aph, bh0);
                mma_bf16(oacc[2*g2],   aph, bl0);
                mma_bf16(oacc[2*g2],   apl, bh0);
                mma_bf16(oacc[2*g2+1], aph, bh1);
                mma_bf16(oacc[2*g2+1], aph, bl1);
                mma_bf16(oacc[2*g2+1], apl, bh1);
            }
        }
        __syncthreads();
    }

    // ---- epilogue: z[b][s][h*64+d] as bf16 hi/lo ----
    float inv0 = 1.0f / l0, inv1 = 1.0f / l1;
    const int bb = bh >> 4, hh = bh & 15;
    const int r = qBase + warp*16 + (lane >> 2);
    #pragma unroll
    for (int j = 0; j < 8; j++) {
        int d = hh*DH_ + j*8 + (lane & 3)*2;
        size_t a0 = ((size_t)(bb*S_ + r))*HD + d;
        size_t a1 = ((size_t)(bb*S_ + r + 8))*HD + d;
        unsigned ph, pl;
        split_pack(oacc[j][0]*inv0, oacc[j][1]*inv0, ph, pl);
        *(unsigned*)&g_zh[a0] = ph; *(unsigned*)&g_zl[a0] = pl;
        split_pack(oacc[j][2]*inv1, oacc[j][3]*inv1, ph, pl);
        *(unsigned*)&g_zh[a1] = ph; *(unsigned*)&g_zl[a1] = pl;
    }
}

// ============================================================================
// Launch
// ============================================================================
extern "C" void kernel_launch(void* const* d_in, const int* in_sizes, int n_in,
                              void* d_out, int out_size)
{
    const float* x  = (const float*)d_in[0];
    const float* Wq = (const float*)d_in[1];
    const float* bq = (const float*)d_in[2];
    const float* Wk = (const float*)d_in[3];
    const float* bk = (const float*)d_in[4];
    const float* Wv = (const float*)d_in[5];
    const float* bv = (const float*)d_in[6];
    const float* Wo = (const float*)d_in[7];
    const float* bo = (const float*)d_in[8];
    float* out = (float*)d_out;

    cudaFuncSetAttribute(gemm_qkv2,
        cudaFuncAttributeMaxDynamicSharedMemorySize, GEMM_SMEM_BYTES);
    cudaFuncSetAttribute(gemm_out2,
        cudaFuncAttributeMaxDynamicSharedMemorySize, GEMM_SMEM_BYTES);
    cudaFuncSetAttribute(attn2,
        cudaFuncAttributeMaxDynamicSharedMemorySize, ATTN_SMEM_BYTES);

    prep_split<<<4096, 256>>>(x, Wq, bq, Wk, bk, Wv, bv, Wo);
    gemm_qkv2<<<dim3(NQKV/128, MT/128), 256, GEMM_SMEM_BYTES>>>();
    attn2<<<dim3(S_/128, B_*H_), 256, ATTN_SMEM_BYTES>>>();
    gemm_out2<<<dim3(E_/128, MT/128), 256, GEMM_SMEM_BYTES>>>(bo, out);
}